// round 1
// baseline (speedup 1.0000x reference)
#include <cuda_runtime.h>
#include <math.h>

// Problem constants
#define Bn   32768
#define Nn   14
#define Fd   128
#define Cd   128
#define Ed   64
#define Et   78            // Ed + Nn self loops
#define Mrows (Bn * Nn)    // 458752 = 3584 * 128

// Scratch: two ping-pong activation buffers + collapsed head weights.
__device__ float g_buf0[(size_t)Mrows * Cd];   // Hpre1 / Hpre2
__device__ float g_h1  [(size_t)Mrows * Cd];   // relu'd layer-1 output
__device__ float g_wlp [Nn * Cd];              // Wl @ Wp  (1792)
__device__ float g_c0;                         // bl @ Wp + bp

// ---------------------------------------------------------------------------
// Collapse the prediction head: wlp = Wl @ Wp, c0 = bl . Wp + bp
// ---------------------------------------------------------------------------
__global__ void wlp_kernel(const float* __restrict__ Wl,
                           const float* __restrict__ Wp,
                           const float* __restrict__ bl,
                           const float* __restrict__ bp)
{
    int idx = blockIdx.x * blockDim.x + threadIdx.x;
    if (idx < Nn * Cd) {
        const float* row = Wl + (size_t)idx * 64;
        float s = 0.f;
        #pragma unroll
        for (int j = 0; j < 64; ++j) s = fmaf(row[j], Wp[j], s);
        g_wlp[idx] = s;
    }
    if (idx == 0) {
        float s = bp[0];
        #pragma unroll
        for (int j = 0; j < 64; ++j) s = fmaf(bl[j], Wp[j], s);
        g_c0 = s;
    }
}

// ---------------------------------------------------------------------------
// SGEMM: C[M,128] = A[M,128] @ B[128,128], M multiple of 128.
// 128x128 tile, BK=8, 256 threads, 8x8 per thread, double-buffered smem.
// ---------------------------------------------------------------------------
__global__ __launch_bounds__(256, 2) void sgemm128(
    const float* __restrict__ A,
    const float* __restrict__ Bm,
    float* __restrict__ C)
{
    __shared__ __align__(16) float As[2][8][132];   // padded: conflict-free stores
    __shared__ __align__(16) float Bs[2][8][128];

    const int tid  = threadIdx.x;
    const size_t row0 = (size_t)blockIdx.x * 128;

    // A tile load mapping: one float4 along K per thread
    const int am = tid >> 1;            // 0..127 (tile row)
    const int ak = (tid & 1) << 2;      // 0 or 4 (k offset)
    // B tile load mapping: one float4 along N per thread
    const int bk = tid >> 5;            // 0..7
    const int bnc = (tid & 31) << 2;    // 0..124

    const float* Ap = A + (row0 + am) * 128 + ak;
    const float* Bp = Bm + (size_t)bk * 128 + bnc;

    // compute mapping: 16x16 thread grid, 4+4 rows / 4+4 cols split
    const int tx = (tid & 15) << 2;     // col base
    const int ty = (tid >> 4) << 2;     // row base

    float acc[8][8];
    #pragma unroll
    for (int i = 0; i < 8; ++i)
        #pragma unroll
        for (int j = 0; j < 8; ++j) acc[i][j] = 0.f;

    // preload k-tile 0
    float4 aR = *(const float4*)Ap;
    float4 bR = *(const float4*)Bp;
    As[0][ak + 0][am] = aR.x; As[0][ak + 1][am] = aR.y;
    As[0][ak + 2][am] = aR.z; As[0][ak + 3][am] = aR.w;
    *(float4*)(&Bs[0][bk][bnc]) = bR;
    __syncthreads();

    int buf = 0;
    #pragma unroll 1
    for (int kt = 0; kt < 16; ++kt) {
        float4 aN, bN;
        if (kt < 15) {
            aN = *(const float4*)(Ap + (kt + 1) * 8);
            bN = *(const float4*)(Bp + (size_t)(kt + 1) * 8 * 128);
        }
        #pragma unroll
        for (int k = 0; k < 8; ++k) {
            float af[8], bf[8];
            *(float4*)&af[0] = *(const float4*)(&As[buf][k][ty]);
            *(float4*)&af[4] = *(const float4*)(&As[buf][k][ty + 64]);
            *(float4*)&bf[0] = *(const float4*)(&Bs[buf][k][tx]);
            *(float4*)&bf[4] = *(const float4*)(&Bs[buf][k][tx + 64]);
            #pragma unroll
            for (int i = 0; i < 8; ++i)
                #pragma unroll
                for (int j = 0; j < 8; ++j)
                    acc[i][j] = fmaf(af[i], bf[j], acc[i][j]);
        }
        if (kt < 15) {
            buf ^= 1;
            As[buf][ak + 0][am] = aN.x; As[buf][ak + 1][am] = aN.y;
            As[buf][ak + 2][am] = aN.z; As[buf][ak + 3][am] = aN.w;
            *(float4*)(&Bs[buf][bk][bnc]) = bN;
            __syncthreads();
        }
    }

    #pragma unroll
    for (int ih = 0; ih < 2; ++ih)
        #pragma unroll
        for (int i = 0; i < 4; ++i) {
            size_t r = row0 + ty + ih * 64 + i;
            float4 v0 = make_float4(acc[ih * 4 + i][0], acc[ih * 4 + i][1],
                                    acc[ih * 4 + i][2], acc[ih * 4 + i][3]);
            float4 v1 = make_float4(acc[ih * 4 + i][4], acc[ih * 4 + i][5],
                                    acc[ih * 4 + i][6], acc[ih * 4 + i][7]);
            *(float4*)(&C[r * 128 + tx])      = v0;
            *(float4*)(&C[r * 128 + tx + 64]) = v1;
        }
}

// ---------------------------------------------------------------------------
// GAT scatter layer: one CTA per batch, 128 threads (thread = channel).
// L2 variant additionally emits attn + fused prediction head.
// ---------------------------------------------------------------------------
template <bool LAYER2>
__global__ __launch_bounds__(128) void gat_kernel(
    const float* __restrict__ Hpre,      // [B, N, C] pre-aggregation features (x @ W)
    const int*   __restrict__ edges,     // [B, E, 2]
    const float* __restrict__ a_s,
    const float* __restrict__ a_d,
    const float* __restrict__ bias,
    float* __restrict__ out_h,           // layer1: [B, N, C]
    float* __restrict__ out_pred,        // layer2: [B]
    float* __restrict__ out_attn)        // layer2: [B, N, N]
{
    __shared__ float hs [Nn * Cd];
    __shared__ float h2s[Nn * Cd];
    __shared__ float asv[Cd], adv[Cd];
    __shared__ float asn[16], adn[16];
    __shared__ int   es[Et], ed[Et];
    __shared__ float lg[Et];
    __shared__ float mC[Nn], zC[Nn];
    __shared__ float Am[Nn * Nn];
    __shared__ float red[4];

    const int tid = threadIdx.x;
    const int b   = blockIdx.x;
    const size_t hbase = (size_t)b * (Nn * Cd);

    // stage node features + attention vectors
    #pragma unroll
    for (int i = 0; i < Nn; ++i) hs[i * Cd + tid] = Hpre[hbase + i * Cd + tid];
    asv[tid] = a_s[tid];
    adv[tid] = a_d[tid];
    const float bc = bias[tid];
    __syncthreads();

    // per-node src/dst scores: warp w handles nodes w, w+4, ...
    {
        const int w = tid >> 5, l = tid & 31;
        for (int n = w; n < Nn; n += 4) {
            float ps = 0.f, pd = 0.f;
            #pragma unroll
            for (int j = 0; j < 4; ++j) {
                float hv = hs[n * Cd + l + 32 * j];
                ps = fmaf(hv, asv[l + 32 * j], ps);
                pd = fmaf(hv, adv[l + 32 * j], pd);
            }
            #pragma unroll
            for (int o = 16; o > 0; o >>= 1) {
                ps += __shfl_xor_sync(0xffffffffu, ps, o);
                pd += __shfl_xor_sync(0xffffffffu, pd, o);
            }
            if (l == 0) { asn[n] = ps; adn[n] = pd; }
        }
    }
    __syncthreads();

    // edge logits (E real edges + N self loops)
    if (tid < Et) {
        int s, d;
        if (tid < Ed) {
            const int* ep = edges + (size_t)b * (Ed * 2) + tid * 2;
            s = ep[0]; d = ep[1];
        } else {
            s = d = tid - Ed;
        }
        es[tid] = s; ed[tid] = d;
        float x = asn[s] + adn[d];
        lg[tid] = (x > 0.f) ? x : 0.2f * x;       // leaky_relu(0.2)
    }
    // zero attn output region (poisoned by harness)
    if (LAYER2) {
        float* ap = out_attn + (size_t)b * (Nn * Nn);
        if (tid < Nn * Nn) ap[tid] = 0.f;
        if (tid + 128 < Nn * Nn) ap[tid + 128] = 0.f;
    }
    __syncthreads();

    // per-dst softmax stats (threads 0..13) + Am zeroing (threads 14..127)
    if (tid < Nn) {
        float mm = -1e30f;
        for (int e = 0; e < Et; ++e) if (ed[e] == tid) mm = fmaxf(mm, lg[e]);
        float zz = 0.f;
        for (int e = 0; e < Et; ++e) if (ed[e] == tid) zz += expf(lg[e] - mm);
        mC[tid] = mm; zC[tid] = zz;
    } else {
        int j = tid - Nn;                 // 0..113
        Am[j] = 0.f;
        if (j + 114 < Nn * Nn) Am[j + 114] = 0.f;
    }
    __syncthreads();

    // alpha, scatter into dense [dst][src] attention matrix (+ attn output)
    if (tid < Et) {
        float a = expf(lg[tid] - mC[ed[tid]]) / zC[ed[tid]];
        atomicAdd(&Am[ed[tid] * Nn + es[tid]], a);
        if (LAYER2)
            out_attn[(size_t)b * (Nn * Nn) + es[tid] * Nn + ed[tid]] = a;
    }
    __syncthreads();

    // aggregate: out[n] = Am[n,:] @ hs + bias   (thread = channel c)
    if (!LAYER2) {
        for (int n = 0; n < Nn; ++n) {
            float acc = bc;
            #pragma unroll
            for (int s = 0; s < Nn; ++s)
                acc = fmaf(Am[n * Nn + s], hs[s * Cd + tid], acc);
            out_h[hbase + n * Cd + tid] = fmaxf(acc, 0.f);   // relu
        }
    } else {
        for (int n = 0; n < Nn; ++n) {
            float acc = bc;
            #pragma unroll
            for (int s = 0; s < Nn; ++s)
                acc = fmaf(Am[n * Nn + s], hs[s * Cd + tid], acc);
            h2s[n * Cd + tid] = acc;
        }
        __syncthreads();
        // fused prediction head: sigmoid(h2_flat . wlp + c0)
        float p = 0.f;
        #pragma unroll
        for (int n = 0; n < Nn; ++n)
            p = fmaf(h2s[n * Cd + tid], g_wlp[n * Cd + tid], p);
        #pragma unroll
        for (int o = 16; o > 0; o >>= 1)
            p += __shfl_xor_sync(0xffffffffu, p, o);
        if ((tid & 31) == 0) red[tid >> 5] = p;
        __syncthreads();
        if (tid == 0) {
            float t = red[0] + red[1] + red[2] + red[3] + g_c0;
            out_pred[b] = 1.f / (1.f + expf(-t));
        }
    }
}

// ---------------------------------------------------------------------------
extern "C" void kernel_launch(void* const* d_in, const int* in_sizes, int n_in,
                              void* d_out, int out_size)
{
    const float* feature = (const float*)d_in[0];
    const int*   edges   = (const int*)  d_in[1];
    const float* W1      = (const float*)d_in[2];
    const float* a_s1    = (const float*)d_in[3];
    const float* a_d1    = (const float*)d_in[4];
    const float* b1      = (const float*)d_in[5];
    const float* W2      = (const float*)d_in[6];
    const float* a_s2    = (const float*)d_in[7];
    const float* a_d2    = (const float*)d_in[8];
    const float* b2      = (const float*)d_in[9];
    const float* Wl      = (const float*)d_in[10];
    const float* bl      = (const float*)d_in[11];
    const float* Wp      = (const float*)d_in[12];
    const float* bp      = (const float*)d_in[13];

    float* out  = (float*)d_out;
    float* pred = out;            // [B]     (reference returns (pred, attn))
    float* attn = out + Bn;       // [B,N,N]

    void *p_buf0 = nullptr, *p_h1 = nullptr;
    cudaGetSymbolAddress(&p_buf0, g_buf0);
    cudaGetSymbolAddress(&p_h1, g_h1);
    float* buf0 = (float*)p_buf0;
    float* h1   = (float*)p_h1;

    // 1. collapse prediction head
    wlp_kernel<<<14, 128>>>(Wl, Wp, bl, bp);

    // 2. Hpre1 = feature @ W1
    sgemm128<<<Mrows / 128, 256>>>(feature, W1, buf0);

    // 3. GAT layer 1 (relu epilogue)
    gat_kernel<false><<<Bn, 128>>>(buf0, edges, a_s1, a_d1, b1, h1, nullptr, nullptr);

    // 4. Hpre2 = h1 @ W2
    sgemm128<<<Mrows / 128, 256>>>(h1, W2, buf0);

    // 5. GAT layer 2 + attn output + fused sigmoid head
    gat_kernel<true><<<Bn, 128>>>(buf0, edges, a_s2, a_d2, b2, nullptr, pred, attn);
}

// round 4
// speedup vs baseline: 1.8822x; 1.8822x over previous
#include <cuda_runtime.h>
#include <cuda_bf16.h>
#include <cstdint>
#include <math.h>

// Problem constants
#define Bn   32768
#define Nn   14
#define Ed   64
#define Cd   128
#define Mrows (Bn * 14)    // 458752 = 3584 * 128

#define WS   136           // padded bf16 row stride (272B: 16B-aligned, +8 bank shift)

// ---------------------------------------------------------------------------
// Scratch (__device__ globals: no allocation allowed). 16B-aligned wrappers so
// float4/uint4 vector accesses are legal.
// ---------------------------------------------------------------------------
struct __align__(16) FBuf  { float f[(size_t)Mrows * Cd]; };
struct __align__(16) WBuf  { __nv_bfloat16 h[128 * WS]; };
struct __align__(16) WlpBuf{ float f[Nn * Cd]; };

__device__ FBuf   g_buf0;                      // Hpre1 / Hpre2
__device__ FBuf   g_h1;                        // relu'd layer-1 output
__device__ WlpBuf g_wlp;                       // Wl @ Wp
__device__ float  g_c0;                        // bl @ Wp + bp
__device__ WBuf   g_w1hi, g_w1lo, g_w2hi, g_w2lo;

// ---------------------------------------------------------------------------
// Helpers
// ---------------------------------------------------------------------------
__device__ __forceinline__ void cvt_hi_lo(float f, __nv_bfloat16& hi, __nv_bfloat16& lo)
{
    hi = __float2bfloat16(f);
    lo = __float2bfloat16(f - __bfloat162float(hi));
}
__device__ __forceinline__ void cvt_hi_lo2(float f0, float f1, uint32_t& hi, uint32_t& lo)
{
    __nv_bfloat16 h0, l0, h1, l1;
    cvt_hi_lo(f0, h0, l0);
    cvt_hi_lo(f1, h1, l1);
    __nv_bfloat162 hp = __halves2bfloat162(h0, h1);
    __nv_bfloat162 lp = __halves2bfloat162(l0, l1);
    hi = *reinterpret_cast<uint32_t*>(&hp);
    lo = *reinterpret_cast<uint32_t*>(&lp);
}

// monotone float<->uint key for atomicMax-based max
__device__ __forceinline__ unsigned fkey(float x)
{
    unsigned u = __float_as_uint(x);
    return u ^ ((unsigned)(((int)u) >> 31) | 0x80000000u);
}
__device__ __forceinline__ float kinv(unsigned k)
{
    unsigned u = k ^ ((k & 0x80000000u) ? 0x80000000u : 0xFFFFFFFFu);
    return __uint_as_float(u);
}

// m16n8k16 bf16 MMA (base-target HMMA, valid on plain sm_103)
__device__ __forceinline__ void mma16816(float* d, const uint32_t* a,
                                         uint32_t b0, uint32_t b1)
{
    asm volatile(
        "mma.sync.aligned.m16n8k16.row.col.f32.bf16.bf16.f32 "
        "{%0,%1,%2,%3}, {%4,%5,%6,%7}, {%8,%9}, {%0,%1,%2,%3};"
        : "+f"(d[0]), "+f"(d[1]), "+f"(d[2]), "+f"(d[3])
        : "r"(a[0]), "r"(a[1]), "r"(a[2]), "r"(a[3]), "r"(b0), "r"(b1));
}

// ---------------------------------------------------------------------------
// Weight prep: W[k=128, n=128] row-major fp32 -> hi/lo bf16 images [n][k] padded
// ---------------------------------------------------------------------------
__global__ void prep_w_kernel(const float* __restrict__ W,
                              __nv_bfloat16* __restrict__ ohi,
                              __nv_bfloat16* __restrict__ olo)
{
    int idx = blockIdx.x * blockDim.x + threadIdx.x;   // 0..16383
    if (idx >= 128 * 128) return;
    int n = idx >> 7, k = idx & 127;
    float w = W[k * 128 + n];
    __nv_bfloat16 hi, lo;
    cvt_hi_lo(w, hi, lo);
    ohi[n * WS + k] = hi;
    olo[n * WS + k] = lo;
}

// ---------------------------------------------------------------------------
// Collapse prediction head: wlp = Wl @ Wp, c0 = bl . Wp + bp
// ---------------------------------------------------------------------------
__global__ void wlp_kernel(const float* __restrict__ Wl,
                           const float* __restrict__ Wp,
                           const float* __restrict__ bl,
                           const float* __restrict__ bp)
{
    int idx = blockIdx.x * blockDim.x + threadIdx.x;
    if (idx < Nn * Cd) {
        const float* row = Wl + (size_t)idx * 64;
        float s = 0.f;
        #pragma unroll
        for (int j = 0; j < 64; ++j) s = fmaf(row[j], Wp[j], s);
        g_wlp.f[idx] = s;
    }
    if (idx == 0) {
        float s = bp[0];
        #pragma unroll
        for (int j = 0; j < 64; ++j) s = fmaf(bl[j], Wp[j], s);
        g_c0 = s;
    }
}

// ---------------------------------------------------------------------------
// Tensor-core GEMM: C[M,128] = A[M,128] @ W[128,128], split-bf16 (3 passes:
// Ahi*Bhi + Ahi*Blo + Alo*Bhi). CTA: 256 threads, tile 128x128, warp 32x64.
// ---------------------------------------------------------------------------
#define TG_SMEM (4 * 128 * WS * 2)   // 139264 bytes

__global__ __launch_bounds__(256) void tgemm_kernel(
    const float* __restrict__ A,
    const __nv_bfloat16* __restrict__ whi,
    const __nv_bfloat16* __restrict__ wlo,
    float* __restrict__ C)
{
    extern __shared__ __align__(16) uint8_t smem_raw[];
    __nv_bfloat16* Ahi = (__nv_bfloat16*)smem_raw;
    __nv_bfloat16* Alo = Ahi + 128 * WS;
    __nv_bfloat16* Bhi = Alo + 128 * WS;
    __nv_bfloat16* Blo = Bhi + 128 * WS;

    const int tid = threadIdx.x;
    const size_t row0 = (size_t)blockIdx.x * 128;

    // copy pre-converted weight images (2176 uint4 each)
    {
        const uint4* s1 = (const uint4*)whi;
        const uint4* s2 = (const uint4*)wlo;
        uint4* d1 = (uint4*)Bhi;
        uint4* d2 = (uint4*)Blo;
        #pragma unroll
        for (int i = 0; i < 9; ++i) {
            int j = tid + 256 * i;
            if (j < 2176) { d1[j] = s1[j]; d2[j] = s2[j]; }
        }
    }

    // load + split-convert A tile (128x128 fp32)
    {
        const float* Ab = A + row0 * 128;
        #pragma unroll
        for (int it = 0; it < 16; ++it) {
            int f = tid + 256 * it;            // float4 id 0..4095
            int row = f >> 5, c4 = (f & 31) << 2;
            float4 v = *(const float4*)&Ab[row * 128 + c4];
            uint32_t h0, l0, h1, l1;
            cvt_hi_lo2(v.x, v.y, h0, l0);
            cvt_hi_lo2(v.z, v.w, h1, l1);
            *(uint2*)&Ahi[row * WS + c4] = make_uint2(h0, h1);
            *(uint2*)&Alo[row * WS + c4] = make_uint2(l0, l1);
        }
    }
    __syncthreads();

    const int w = tid >> 5, lane = tid & 31;
    const int g = lane >> 2, tig = lane & 3;
    const int mrow0 = (w >> 1) * 32;
    const int ncol0 = (w & 1) * 64;

    float d[2][8][4];
    #pragma unroll
    for (int mb = 0; mb < 2; ++mb)
        #pragma unroll
        for (int nb = 0; nb < 8; ++nb)
            #pragma unroll
            for (int j = 0; j < 4; ++j) d[mb][nb][j] = 0.f;

    const __nv_bfloat16* Ap3[3] = { Ahi, Ahi, Alo };
    const __nv_bfloat16* Bp3[3] = { Bhi, Blo, Bhi };

    #pragma unroll
    for (int pass = 0; pass < 3; ++pass) {
        const __nv_bfloat16* Abase = Ap3[pass];
        const __nv_bfloat16* Bbase = Bp3[pass];
        #pragma unroll
        for (int k0 = 0; k0 < 128; k0 += 16) {
            uint32_t a[2][4];
            #pragma unroll
            for (int mb = 0; mb < 2; ++mb) {
                const __nv_bfloat16* ap =
                    Abase + (mrow0 + mb * 16 + g) * WS + k0 + 2 * tig;
                a[mb][0] = *(const uint32_t*)ap;
                a[mb][1] = *(const uint32_t*)(ap + 8 * WS);
                a[mb][2] = *(const uint32_t*)(ap + 8);
                a[mb][3] = *(const uint32_t*)(ap + 8 * WS + 8);
            }
            #pragma unroll
            for (int nb = 0; nb < 8; ++nb) {
                const __nv_bfloat16* bp =
                    Bbase + (ncol0 + nb * 8 + g) * WS + k0 + 2 * tig;
                uint32_t b0 = *(const uint32_t*)bp;
                uint32_t b1 = *(const uint32_t*)(bp + 8);
                mma16816(d[0][nb], a[0], b0, b1);
                mma16816(d[1][nb], a[1], b0, b1);
            }
        }
    }

    // epilogue: direct float2 stores
    float* Cb = C + row0 * 128;
    #pragma unroll
    for (int mb = 0; mb < 2; ++mb) {
        #pragma unroll
        for (int nb = 0; nb < 8; ++nb) {
            int r = mrow0 + mb * 16 + g;
            int c = ncol0 + nb * 8 + 2 * tig;
            *(float2*)&Cb[r * 128 + c]       = make_float2(d[mb][nb][0], d[mb][nb][1]);
            *(float2*)&Cb[(r + 8) * 128 + c] = make_float2(d[mb][nb][2], d[mb][nb][3]);
        }
    }
}

// ---------------------------------------------------------------------------
// GAT scatter layer: warp-per-batch. CTA = 8 warps = 8 batches.
// Lane owns channels [4*lane, 4*lane+4). No block barriers.
// ---------------------------------------------------------------------------
#define GW 8

template <bool LAYER2>
__global__ __launch_bounds__(256) void gat_kernel(
    const float* __restrict__ Hpre,
    const int*   __restrict__ edges,
    const float* __restrict__ a_s,
    const float* __restrict__ a_d,
    const float* __restrict__ bias,
    float* __restrict__ out_h,
    float* __restrict__ out_pred,
    float* __restrict__ out_attn)
{
    __shared__ float    s_asn[GW][16], s_adn[GW][16], s_z[GW][16];
    __shared__ unsigned s_mk[GW][16];
    __shared__ float    s_Am[GW][200];
    __shared__ __align__(16) float s_At[GW][196];

    const int tid = threadIdx.x;
    const int w = tid >> 5, lane = tid & 31;
    const int b = blockIdx.x * GW + w;

    // zero per-warp state
    #pragma unroll
    for (int i = 0; i < 7; ++i) {
        int j = lane + 32 * i;
        if (j < 196) { s_Am[w][j] = 0.f; if (LAYER2) s_At[w][j] = 0.f; }
    }
    if (lane < 14) { s_mk[w][lane] = 0u; s_z[w][lane] = 0.f; }

    // stage node features into registers (lane owns 4 channels)
    const float* hb = Hpre + (size_t)b * (Nn * Cd);
    float4 v[Nn];
    #pragma unroll
    for (int n = 0; n < Nn; ++n)
        v[n] = *(const float4*)&hb[n * Cd + lane * 4];
    const float4 as4 = *(const float4*)&a_s[lane * 4];
    const float4 ad4 = *(const float4*)&a_d[lane * 4];
    const float4 bi4 = *(const float4*)&bias[lane * 4];

    // per-node src/dst scores (warp reduce)
    float pa[Nn], pd[Nn];
    #pragma unroll
    for (int n = 0; n < Nn; ++n) {
        pa[n] = v[n].x * as4.x + v[n].y * as4.y + v[n].z * as4.z + v[n].w * as4.w;
        pd[n] = v[n].x * ad4.x + v[n].y * ad4.y + v[n].z * ad4.z + v[n].w * ad4.w;
    }
    #pragma unroll
    for (int o = 16; o > 0; o >>= 1) {
        #pragma unroll
        for (int n = 0; n < Nn; ++n) {
            pa[n] += __shfl_xor_sync(0xffffffffu, pa[n], o);
            pd[n] += __shfl_xor_sync(0xffffffffu, pd[n], o);
        }
    }
    if (lane == 0) {
        #pragma unroll
        for (int n = 0; n < Nn; ++n) { s_asn[w][n] = pa[n]; s_adn[w][n] = pd[n]; }
    }
    __syncwarp();

    // edges: lanes cover 78 edges in 3 rounds (64 real + 14 self loops)
    const int* eb = edges + (size_t)b * (Ed * 2);
    int  es_[3], ed_[3];
    float lg_[3], ev_[3];
    bool act[3];
    #pragma unroll
    for (int r = 0; r < 3; ++r) {
        int e = lane + 32 * r;
        act[r] = (e < 78);
        es_[r] = 0; ed_[r] = 0; lg_[r] = 0.f;
        if (act[r]) {
            int s, dd;
            if (e < Ed) { int2 p = *(const int2*)&eb[2 * e]; s = p.x; dd = p.y; }
            else        { s = dd = e - Ed; }
            float x = s_asn[w][s] + s_adn[w][dd];
            x = (x > 0.f) ? x : 0.2f * x;
            es_[r] = s; ed_[r] = dd; lg_[r] = x;
            atomicMax(&s_mk[w][dd], fkey(x));
        }
    }
    __syncwarp();
    #pragma unroll
    for (int r = 0; r < 3; ++r) {
        if (act[r]) {
            float m = kinv(s_mk[w][ed_[r]]);
            ev_[r] = expf(lg_[r] - m);
            atomicAdd(&s_z[w][ed_[r]], ev_[r]);
        }
    }
    __syncwarp();
    #pragma unroll
    for (int r = 0; r < 3; ++r) {
        if (act[r]) {
            float al = ev_[r] / s_z[w][ed_[r]];
            atomicAdd(&s_Am[w][ed_[r] * Nn + es_[r]], al);
            if (LAYER2) s_At[w][es_[r] * Nn + ed_[r]] = al;
        }
    }
    __syncwarp();

    // aggregate: out[n] = bias + sum_s Am[n][s] * h[s]
    if (!LAYER2) {
        float* ob = out_h + (size_t)b * (Nn * Cd);
        #pragma unroll
        for (int n = 0; n < Nn; ++n) {
            float4 acc = bi4;
            #pragma unroll
            for (int s = 0; s < Nn; ++s) {
                float am = s_Am[w][n * Nn + s];
                acc.x = fmaf(am, v[s].x, acc.x);
                acc.y = fmaf(am, v[s].y, acc.y);
                acc.z = fmaf(am, v[s].z, acc.z);
                acc.w = fmaf(am, v[s].w, acc.w);
            }
            acc.x = fmaxf(acc.x, 0.f); acc.y = fmaxf(acc.y, 0.f);
            acc.z = fmaxf(acc.z, 0.f); acc.w = fmaxf(acc.w, 0.f);
            *(float4*)&ob[n * Cd + lane * 4] = acc;
        }
    } else {
        float p = 0.f;
        #pragma unroll
        for (int n = 0; n < Nn; ++n) {
            float4 acc = bi4;
            #pragma unroll
            for (int s = 0; s < Nn; ++s) {
                float am = s_Am[w][n * Nn + s];
                acc.x = fmaf(am, v[s].x, acc.x);
                acc.y = fmaf(am, v[s].y, acc.y);
                acc.z = fmaf(am, v[s].z, acc.z);
                acc.w = fmaf(am, v[s].w, acc.w);
            }
            float4 wv = *(const float4*)&g_wlp.f[n * Cd + lane * 4];
            p += acc.x * wv.x + acc.y * wv.y + acc.z * wv.z + acc.w * wv.w;
        }
        #pragma unroll
        for (int o = 16; o > 0; o >>= 1)
            p += __shfl_xor_sync(0xffffffffu, p, o);
        if (lane == 0)
            out_pred[b] = 1.f / (1.f + expf(-(p + g_c0)));
        __syncwarp();
        // write attention matrix (196 floats = 49 float4)
        float* ab = out_attn + (size_t)b * (Nn * Nn);
        #pragma unroll
        for (int i = 0; i < 2; ++i) {
            int j = lane + 32 * i;
            if (j < 49)
                *(float4*)&ab[4 * j] = *(const float4*)&s_At[w][4 * j];
        }
    }
}

// ---------------------------------------------------------------------------
extern "C" void kernel_launch(void* const* d_in, const int* in_sizes, int n_in,
                              void* d_out, int out_size)
{
    const float* feature = (const float*)d_in[0];
    const int*   edges   = (const int*)  d_in[1];
    const float* W1      = (const float*)d_in[2];
    const float* a_s1    = (const float*)d_in[3];
    const float* a_d1    = (const float*)d_in[4];
    const float* b1      = (const float*)d_in[5];
    const float* W2      = (const float*)d_in[6];
    const float* a_s2    = (const float*)d_in[7];
    const float* a_d2    = (const float*)d_in[8];
    const float* b2      = (const float*)d_in[9];
    const float* Wl      = (const float*)d_in[10];
    const float* bl      = (const float*)d_in[11];
    const float* Wp      = (const float*)d_in[12];
    const float* bp      = (const float*)d_in[13];

    float* out  = (float*)d_out;
    float* pred = out;            // [B]
    float* attn = out + Bn;       // [B,N,N]

    void *p_buf0, *p_h1, *p_w1h, *p_w1l, *p_w2h, *p_w2l;
    cudaGetSymbolAddress(&p_buf0, g_buf0);
    cudaGetSymbolAddress(&p_h1,   g_h1);
    cudaGetSymbolAddress(&p_w1h,  g_w1hi);
    cudaGetSymbolAddress(&p_w1l,  g_w1lo);
    cudaGetSymbolAddress(&p_w2h,  g_w2hi);
    cudaGetSymbolAddress(&p_w2l,  g_w2lo);
    float* buf0 = (float*)p_buf0;
    float* h1   = (float*)p_h1;
    __nv_bfloat16* w1h = (__nv_bfloat16*)p_w1h;
    __nv_bfloat16* w1l = (__nv_bfloat16*)p_w1l;
    __nv_bfloat16* w2h = (__nv_bfloat16*)p_w2h;
    __nv_bfloat16* w2l = (__nv_bfloat16*)p_w2l;

    cudaFuncSetAttribute(tgemm_kernel,
                         cudaFuncAttributeMaxDynamicSharedMemorySize, TG_SMEM);

    // 0. pre-convert weights into padded bf16 hi/lo images
    prep_w_kernel<<<128, 128>>>(W1, w1h, w1l);
    prep_w_kernel<<<128, 128>>>(W2, w2h, w2l);

    // 1. collapse prediction head
    wlp_kernel<<<14, 128>>>(Wl, Wp, bl, bp);

    // 2. Hpre1 = feature @ W1  (HMMA split-bf16)
    tgemm_kernel<<<Mrows / 128, 256, TG_SMEM>>>(feature, w1h, w1l, buf0);

    // 3. GAT layer 1 (relu epilogue)
    gat_kernel<false><<<Bn / GW, 256>>>(buf0, edges, a_s1, a_d1, b1, h1, nullptr, nullptr);

    // 4. Hpre2 = h1 @ W2
    tgemm_kernel<<<Mrows / 128, 256, TG_SMEM>>>(h1, w2h, w2l, buf0);

    // 5. GAT layer 2 + attn + fused sigmoid head
    gat_kernel<true><<<Bn / GW, 256>>>(buf0, edges, a_s2, a_d2, b2, nullptr, pred, attn);
}